// round 11
// baseline (speedup 1.0000x reference)
#include <cuda_runtime.h>
#include <cstdint>

// Sinkhorn as diagonal scaling, single persistent cluster kernel.
// out = (s+eps)*u9[r]*v8[c] on valid block, 0 outside.
// v_{2k} = 1/(M^T u_{2k-1}), u_{2k+1} = 1/(M v_{2k}), u0 = 1 on valid rows.
//
// R11: R8 traffic structure (32 clusters x 8 CTAs, 2 sequential batches,
// ~484MB DRAM verified) + three serialization fixes:
//  - cyclic row ownership (r = rank + 8*lidx): all ranks do ceil((nr-rank)/8)
//    rows -> cluster barriers no longer gated by a 128-row rank
//  - interleaved column chunks (half 0 even, half 1 odd 128-col chunks):
//    column trimming balances across warp halves
//  - ONE cluster barrier per pass: acc double-buffered; each CTA reads all 8
//    ranks' partials via DSMEM after the barrier and computes full v locally.

#define NB     64
#define NN     1024
#define EPS    1e-4f
#define CSZ    8       // CTAs per cluster
#define NCLUS  32      // concurrent clusters (batches in flight)
#define LRN    128     // local rows per CTA (cyclic: r = rank + 8*lidx)
#define HRW    16      // local rows per warp
#define GR     4       // rows per phase group

__device__ __forceinline__ uint32_t smem_u32(const void* p) {
    uint32_t a;
    asm("{ .reg .u64 t; cvta.to.shared.u64 t, %1; cvt.u32.u64 %0, t; }"
        : "=r"(a) : "l"(p));
    return a;
}
__device__ __forceinline__ uint32_t mapa_u32(uint32_t local, uint32_t rank) {
    uint32_t r;
    asm("mapa.shared::cluster.u32 %0, %1, %2;" : "=r"(r) : "r"(local), "r"(rank));
    return r;
}
__device__ __forceinline__ float ld_cluster(uint32_t a) {
    float v;
    asm volatile("ld.shared::cluster.f32 %0, [%1];" : "=f"(v) : "r"(a));
    return v;
}
// arrive (no .relaxed) = release, wait = acquire.
#define CLUSTER_SYNC() do {                                        \
    asm volatile("barrier.cluster.arrive.aligned;" ::: "memory");  \
    asm volatile("barrier.cluster.wait.aligned;"   ::: "memory");  \
} while (0)

__global__ void __cluster_dims__(CSZ, 1, 1) __launch_bounds__(512, 2)
sinkhorn_kernel(const float* __restrict__ s,
                float*       __restrict__ out,
                const int*   __restrict__ nrows,
                const int*   __restrict__ ncols)
{
    __shared__ float  v_s[NN];            // full column scales (local copy)
    __shared__ float  acc_s[2][NN];       // double-buffered partial col sums
    __shared__ float  d_s[2][LRN];        // half-row dots per local row
    __shared__ float4 stage[16][128];     // per-warp accumulator staging

    const int tid  = threadIdx.x;
    const int rank = blockIdx.x;          // cluster rank 0..7
    const int clus = blockIdx.y;          // cluster id 0..31
    const int warp = tid >> 5;
    const int lane = tid & 31;
    const int half = warp >> 3;           // chunk parity: 0 = even, 1 = odd
    const int wseq = warp & 7;            // row-group id within half
    const int wrow = wseq * HRW;          // first local row of this warp

    const uint32_t a_acc = smem_u32(acc_s);
    int par = 0;                          // acc buffer parity (runs across batches)

    for (int b = clus; b < NB; b += NCLUS) {
        const int nr = nrows[b];
        const int nc = ncols[b];
        // chunk k = 2f+half covers cols [128k, 128k+128); this lane loads
        // float4 at index k*32+lane (cols 128k+4lane..+3): need 256f < mylim
        const int mylim  = nc - 128 * half - 4 * lane;
        const int nvalid = (nr - rank + 7) >> 3;   // local rows with r < nr

        const float4* sb = (const float4*)(s + (size_t)b * NN * NN);

        // ---- 5 accumulation passes: pass0 (u=1) -> v0; 1..4 -> v2,v4,v6,v8
        for (int pass = 0; pass < 5; pass++) {
            const bool FIRST = (pass == 0);

            // phase 1: half-row dots -> d_s (skipped when u==1)
            if (!FIRST) {
                float4 v4[4];
                const float4* vv = (const float4*)v_s;
#pragma unroll
                for (int f = 0; f < 4; f++)
                    v4[f] = (256 * f < mylim) ? vv[(2 * f + half) * 32 + lane]
                                              : make_float4(0.f, 0.f, 0.f, 0.f);
                for (int g = 0; g < HRW / GR; g++) {
                    const int l0  = wrow + g * GR;
                    const int cnt = min(GR, nvalid - l0);
                    if (cnt <= 0) break;                 // warp-uniform
                    float4 dv[GR];
#pragma unroll
                    for (int i = 0; i < GR; i++)
                        dv[i] = make_float4(0.f, 0.f, 0.f, 0.f);
#pragma unroll
                    for (int i = 0; i < GR; i++) {
                        if (i >= cnt) break;
                        const float4* rp = sb + (size_t)(rank + 8 * (l0 + i)) * 256;
#pragma unroll
                        for (int f = 0; f < 4; f++)
                            if (256 * f < mylim) {
                                float4 x = rp[(2 * f + half) * 32 + lane];
                                dv[i].x += (x.x + EPS) * v4[f].x;
                                dv[i].y += (x.y + EPS) * v4[f].y;
                                dv[i].z += (x.z + EPS) * v4[f].z;
                                dv[i].w += (x.w + EPS) * v4[f].w;
                            }
                    }
                    float d[GR];
#pragma unroll
                    for (int i = 0; i < GR; i++)
                        d[i] = (dv[i].x + dv[i].y) + (dv[i].z + dv[i].w);
#pragma unroll
                    for (int o = 16; o; o >>= 1) {
#pragma unroll
                        for (int i = 0; i < GR; i++)
                            d[i] += __shfl_xor_sync(0xffffffffu, d[i], o);
                    }
                    if (lane == 0) {
                        d_s[half][l0] = d[0];
                        if (cnt > 1) d_s[half][l0 + 1] = d[1];
                        if (cnt > 2) d_s[half][l0 + 2] = d[2];
                        if (cnt > 3) d_s[half][l0 + 3] = d[3];
                    }
                }
            }
            __syncthreads();   // d_s ready; stage/v_s from prev pass consumed

            // phase 2: accumulate column sums with u = 1/(d0+d1)
            float4 acc[4];
#pragma unroll
            for (int f = 0; f < 4; f++) acc[f] = make_float4(0.f, 0.f, 0.f, 0.f);

            for (int g = 0; g < HRW / GR; g++) {
                const int l0  = wrow + g * GR;
                const int cnt = min(GR, nvalid - l0);
                if (cnt <= 0) break;                     // warp-uniform
#pragma unroll
                for (int i = 0; i < GR; i++) {
                    if (i >= cnt) break;
                    const int lr = l0 + i;
                    const float u = FIRST ? 1.0f
                                          : 1.0f / (d_s[0][lr] + d_s[1][lr]);
                    const float4* rp = sb + (size_t)(rank + 8 * lr) * 256;
#pragma unroll
                    for (int f = 0; f < 4; f++)
                        if (256 * f < mylim) {
                            float4 x = rp[(2 * f + half) * 32 + lane];
                            acc[f].x += (x.x + EPS) * u;
                            acc[f].y += (x.y + EPS) * u;
                            acc[f].z += (x.z + EPS) * u;
                            acc[f].w += (x.w + EPS) * u;
                        }
                }
            }

            // CTA reduction into acc_s[par] (full overwrite, no zeroing)
#pragma unroll
            for (int f = 0; f < 4; f++) stage[warp][f * 32 + lane] = acc[f];
            __syncthreads();
            if (tid < 256) {
                const int h = tid >> 7;
                const int j = tid & 127;
                float4 t = stage[h * 8][j];
#pragma unroll
                for (int k = 1; k < 8; k++) {
                    float4 a = stage[h * 8 + k][j];
                    t.x += a.x; t.y += a.y; t.z += a.z; t.w += a.w;
                }
                const int fidx = (2 * (j >> 5) + h) * 32 + (j & 31);
                ((float4*)acc_s[par])[fidx] = t;
            }

            // ONE cluster barrier, then every CTA builds full v locally from
            // all 8 ranks' partials (DSMEM reads; no write-back, no 2nd sync).
            CLUSTER_SYNC();
            {
                const int c0 = tid * 2;
                const uint32_t base = a_acc + (uint32_t)par * (NN * 4) + 4u * c0;
                float s0 = 0.f, s1 = 0.f;
#pragma unroll
                for (int r = 0; r < CSZ; r++) {
                    const uint32_t pa = mapa_u32(base, r);
                    s0 += ld_cluster(pa);
                    s1 += ld_cluster(pa + 4);
                }
                v_s[c0]     = (c0     < nc) ? (1.0f / s0) : 0.0f;
                v_s[c0 + 1] = (c0 + 1 < nc) ? (1.0f / s1) : 0.0f;
            }
            __syncthreads();   // v_s ready; d_s reusable
            par ^= 1;
        }

        // ---- final pass: u9 = 1/(M v8), write out = (s+eps)*u9*v8
        {
            float4 v4[4];
            const float4* vv = (const float4*)v_s;
#pragma unroll
            for (int f = 0; f < 4; f++)
                v4[f] = (256 * f < mylim) ? vv[(2 * f + half) * 32 + lane]
                                          : make_float4(0.f, 0.f, 0.f, 0.f);

            // phase 1: dots for u9
            for (int g = 0; g < HRW / GR; g++) {
                const int l0  = wrow + g * GR;
                const int cnt = min(GR, nvalid - l0);
                if (cnt <= 0) break;
                float4 dv[GR];
#pragma unroll
                for (int i = 0; i < GR; i++)
                    dv[i] = make_float4(0.f, 0.f, 0.f, 0.f);
#pragma unroll
                for (int i = 0; i < GR; i++) {
                    if (i >= cnt) break;
                    const float4* rp = sb + (size_t)(rank + 8 * (l0 + i)) * 256;
#pragma unroll
                    for (int f = 0; f < 4; f++)
                        if (256 * f < mylim) {
                            float4 x = rp[(2 * f + half) * 32 + lane];
                            dv[i].x += (x.x + EPS) * v4[f].x;
                            dv[i].y += (x.y + EPS) * v4[f].y;
                            dv[i].z += (x.z + EPS) * v4[f].z;
                            dv[i].w += (x.w + EPS) * v4[f].w;
                        }
                }
                float d[GR];
#pragma unroll
                for (int i = 0; i < GR; i++)
                    d[i] = (dv[i].x + dv[i].y) + (dv[i].z + dv[i].w);
#pragma unroll
                for (int o = 16; o; o >>= 1) {
#pragma unroll
                    for (int i = 0; i < GR; i++)
                        d[i] += __shfl_xor_sync(0xffffffffu, d[i], o);
                }
                if (lane == 0) {
                    d_s[half][l0] = d[0];
                    if (cnt > 1) d_s[half][l0 + 1] = d[1];
                    if (cnt > 2) d_s[half][l0 + 2] = d[2];
                    if (cnt > 3) d_s[half][l0 + 3] = d[3];
                }
            }
            __syncthreads();

            // phase 2: write all owned rows (zeros for invalid)
            float4* ob = (float4*)(out + (size_t)b * NN * NN);
            const float4 z4 = make_float4(0.f, 0.f, 0.f, 0.f);
            for (int g = 0; g < HRW / GR; g++) {
#pragma unroll
                for (int i = 0; i < GR; i++) {
                    const int lr = wrow + g * GR + i;
                    float4* op = ob + (size_t)(rank + 8 * lr) * 256;
                    if (lr >= nvalid) {                  // invalid row: zeros
#pragma unroll
                        for (int f = 0; f < 4; f++)
                            __stcs(&op[(2 * f + half) * 32 + lane], z4);
                        continue;
                    }
                    const float u = 1.0f / (d_s[0][lr] + d_s[1][lr]);
                    const float4* rp = sb + (size_t)(rank + 8 * lr) * 256;
#pragma unroll
                    for (int f = 0; f < 4; f++) {
                        if (256 * f < mylim) {
                            float4 x = rp[(2 * f + half) * 32 + lane];
                            float4 o;
                            o.x = (x.x + EPS) * u * v4[f].x;
                            o.y = (x.y + EPS) * u * v4[f].y;
                            o.z = (x.z + EPS) * u * v4[f].z;
                            o.w = (x.w + EPS) * u * v4[f].w;
                            __stcs(&op[(2 * f + half) * 32 + lane], o);
                        } else {
                            __stcs(&op[(2 * f + half) * 32 + lane], z4);
                        }
                    }
                }
            }
            __syncthreads();   // d_s reuse next batch
        }
        // Batch-boundary safety: no rank may overwrite acc_s[par] (pass0 of
        // next batch eventually) while a slow peer still reads this batch's
        // partials.
        CLUSTER_SYNC();
    }
}

extern "C" void kernel_launch(void* const* d_in, const int* in_sizes, int n_in,
                              void* d_out, int out_size)
{
    const float* s = (const float*)d_in[0];
    const int *nrows, *ncols;
    if (n_in >= 5) {          // order: s, n1, n2, nrows, ncols
        nrows = (const int*)d_in[3];
        ncols = (const int*)d_in[4];
    } else {                  // fallback: s, nrows, ncols
        nrows = (const int*)d_in[1];
        ncols = (const int*)d_in[2];
    }
    float* out = (float*)d_out;

    sinkhorn_kernel<<<dim3(CSZ, NCLUS), 512>>>(s, out, nrows, ncols);
}